// round 13
// baseline (speedup 1.0000x reference)
#include <cuda_runtime.h>
#include <cuda_bf16.h>
#include <cstdint>

typedef unsigned long long u64;
typedef unsigned int u32;

// ---------------------------------------------------------------------------
// EnrichAttention: bf16x3-split HMMA GEMMs -> softmax(dim=1) -> ctx -> concat
// -> GRU v5 (warp-autonomous cluster recurrence, st.async data-driven sync).
// ---------------------------------------------------------------------------

// scratch layout (floats)
#define OFF_T1 0
#define OFF_A1 4194304      // 16384*256
#define OFF_A2 8388608
#define OFF_M  12582912     // 32*512*512 = 8388608 floats
#define OFF_G  20971520     // 16384*512  = 8388608
#define OFF_XP 29360128     // 16384*768  = 12582912
#define SCRATCH_FLOATS 41943040

__device__ float g_scratch[SCRATCH_FLOATS];

// ---- helpers ----------------------------------------------------------------
__device__ __forceinline__ u32 saddr(const void* p) {
    u32 a;
    asm("{ .reg .u64 t; cvta.to.shared.u64 t, %1; cvt.u32.u64 %0, t; }"
        : "=r"(a) : "l"(p));
    return a;
}
__device__ __forceinline__ void mbar_wait(u32 mbar, u32 parity) {
    u32 done;
    asm volatile(
        "{\n\t.reg .pred p;\n\t"
        "mbarrier.try_wait.parity.acquire.cta.shared::cta.b64 p, [%1], %2;\n\t"
        "selp.b32 %0, 1, 0, p;\n\t}"
        : "=r"(done) : "r"(mbar), "r"(parity) : "memory");
    if (!done) {
        asm volatile(
            "{\n\t.reg .pred P1;\n\t"
            "WL%=:\n\t"
            "mbarrier.try_wait.parity.acquire.cta.shared::cta.b64 P1, [%0], %1, 0x989680;\n\t"
            "@P1 bra.uni WD%=;\n\t"
            "bra.uni WL%=;\n\t"
            "WD%=:\n\t}"
            :: "r"(mbar), "r"(parity) : "memory");
    }
}

// ---------------------------------------------------------------------------
// bf16x3 HMMA GEMM (unchanged from R12 — 65us on the scores GEMM).
// ---------------------------------------------------------------------------
#define LDR 40
#define MAT_ELEMS (128 * LDR)
#define BUF_ELEMS (4 * MAT_ELEMS)
#define GEMM_SMEM (2 * BUF_ELEMS * 2)

__device__ __forceinline__ void split2(float x, float y, u32& hi, u32& lo) {
    __nv_bfloat16 hx = __float2bfloat16_rn(x), hy = __float2bfloat16_rn(y);
    float rx = x - __bfloat162float(hx), ry = y - __bfloat162float(hy);
    __nv_bfloat16 lx = __float2bfloat16_rn(rx), ly = __float2bfloat16_rn(ry);
    hi = ((u32)__bfloat16_as_ushort(hy) << 16) | __bfloat16_as_ushort(hx);
    lo = ((u32)__bfloat16_as_ushort(ly) << 16) | __bfloat16_as_ushort(lx);
}
__device__ __forceinline__ void ldsm4(u32& r0, u32& r1, u32& r2, u32& r3, u32 a) {
    asm volatile("ldmatrix.sync.aligned.m8n8.x4.shared.b16 {%0,%1,%2,%3}, [%4];"
                 : "=r"(r0), "=r"(r1), "=r"(r2), "=r"(r3) : "r"(a));
}
__device__ __forceinline__ void mma_bf16(float* c, const u32* a, const u32* b) {
    asm volatile(
        "mma.sync.aligned.m16n8k16.row.col.f32.bf16.bf16.f32 "
        "{%0,%1,%2,%3}, {%4,%5,%6,%7}, {%8,%9}, {%0,%1,%2,%3};"
        : "+f"(c[0]), "+f"(c[1]), "+f"(c[2]), "+f"(c[3])
        : "r"(a[0]), "r"(a[1]), "r"(a[2]), "r"(a[3]), "r"(b[0]), "r"(b[1]));
}

template<int EPI, bool TRANSB>
__global__ void __launch_bounds__(256) mma_gemm(
    const float* __restrict__ A, const float* __restrict__ B,
    float* __restrict__ C, int K, int lda, int ldb, int ldc,
    long long sA, long long sB, long long sC,
    const float* __restrict__ E, int eN)
{
    extern __shared__ __align__(16) __nv_bfloat16 sm[];
    A += (size_t)blockIdx.z * sA;
    B += (size_t)blockIdx.z * sB;
    C += (size_t)blockIdx.z * sC;

    const int tid = threadIdx.x;
    const int wid = tid >> 5, lane = tid & 31;
    const int wm = wid >> 2, wn = wid & 3;
    const int m0 = blockIdx.y * 128, n0 = blockIdx.x * 128;

    const int ar0 = tid >> 3;
    const int akq = (tid & 7) * 4;
    const int nk  = tid & 31;
    const int nn4 = (tid >> 5) * 4;

    const int q = lane >> 3, lr = lane & 7;
    const int a_t = (lr + (q & 1) * 8) * LDR + (q >> 1) * 8;
    const int b_t = (lr + (q >> 1) * 8) * LDR + (q & 1) * 8;
    const u32 smb = saddr(sm);

    float acc[4][4][4];
#pragma unroll
    for (int mt = 0; mt < 4; mt++)
#pragma unroll
        for (int nt = 0; nt < 4; nt++)
#pragma unroll
            for (int e = 0; e < 4; e++) acc[mt][nt][e] = 0.f;

    const int nch = K >> 5;

    {
        __nv_bfloat16* Ah = sm;
        __nv_bfloat16* Al = sm + MAT_ELEMS;
        __nv_bfloat16* Bh = sm + 2 * MAT_ELEMS;
        __nv_bfloat16* Bl = sm + 3 * MAT_ELEMS;
#pragma unroll
        for (int i = 0; i < 4; i++) {
            const int r = ar0 + i * 32;
            float4 v = *(const float4*)(A + (size_t)(m0 + r) * lda + akq);
            uint2 h, l;
            split2(v.x, v.y, h.x, l.x); split2(v.z, v.w, h.y, l.y);
            *(uint2*)&Ah[r * LDR + akq] = h;
            *(uint2*)&Al[r * LDR + akq] = l;
        }
        if (TRANSB) {
#pragma unroll
            for (int i = 0; i < 4; i++) {
                const int r = ar0 + i * 32;
                float4 v = *(const float4*)(B + (size_t)(n0 + r) * ldb + akq);
                uint2 h, l;
                split2(v.x, v.y, h.x, l.x); split2(v.z, v.w, h.y, l.y);
                *(uint2*)&Bh[r * LDR + akq] = h;
                *(uint2*)&Bl[r * LDR + akq] = l;
            }
        } else {
#pragma unroll
            for (int i = 0; i < 4; i++) {
                const int nb = nn4 + i * 32;
                float4 v = *(const float4*)(B + (size_t)nk * ldb + n0 + nb);
                const float vv[4] = { v.x, v.y, v.z, v.w };
#pragma unroll
                for (int j = 0; j < 4; j++) {
                    __nv_bfloat16 hb = __float2bfloat16_rn(vv[j]);
                    float rres = vv[j] - __bfloat162float(hb);
                    Bh[(nb + j) * LDR + nk] = hb;
                    Bl[(nb + j) * LDR + nk] = __float2bfloat16_rn(rres);
                }
            }
        }
    }
    __syncthreads();

    for (int c = 0; c < nch; c++) {
        const int buf = c & 1;
        const u32 base = smb + buf * (BUF_ELEMS * 2);

        float4 apre[4], bpre[4];
        if (c + 1 < nch) {
            const int k0 = (c + 1) * 32;
#pragma unroll
            for (int i = 0; i < 4; i++)
                apre[i] = *(const float4*)(A + (size_t)(m0 + ar0 + i * 32) * lda + k0 + akq);
            if (TRANSB) {
#pragma unroll
                for (int i = 0; i < 4; i++)
                    bpre[i] = *(const float4*)(B + (size_t)(n0 + ar0 + i * 32) * ldb + k0 + akq);
            } else {
#pragma unroll
                for (int i = 0; i < 4; i++)
                    bpre[i] = *(const float4*)(B + (size_t)(k0 + nk) * ldb + n0 + nn4 + i * 32);
            }
        }

#pragma unroll
        for (int ks = 0; ks < 32; ks += 16) {
            u32 ah[4][4], al[4][4], bh[4][2], bl[4][2];
#pragma unroll
            for (int mt = 0; mt < 4; mt++) {
                const u32 off = (u32)(a_t + (wm * 64 + mt * 16) * LDR + ks) * 2;
                ldsm4(ah[mt][0], ah[mt][1], ah[mt][2], ah[mt][3], base + off);
                ldsm4(al[mt][0], al[mt][1], al[mt][2], al[mt][3],
                      base + off + MAT_ELEMS * 2);
            }
#pragma unroll
            for (int np = 0; np < 2; np++) {
                const u32 off = (u32)(b_t + (wn * 32 + np * 16) * LDR + ks) * 2;
                u32 t0, t1, t2, t3;
                ldsm4(t0, t1, t2, t3, base + off + 2 * MAT_ELEMS * 2);
                bh[2 * np][0] = t0; bh[2 * np][1] = t1;
                bh[2 * np + 1][0] = t2; bh[2 * np + 1][1] = t3;
                ldsm4(t0, t1, t2, t3, base + off + 3 * MAT_ELEMS * 2);
                bl[2 * np][0] = t0; bl[2 * np][1] = t1;
                bl[2 * np + 1][0] = t2; bl[2 * np + 1][1] = t3;
            }
#pragma unroll
            for (int mt = 0; mt < 4; mt++)
#pragma unroll
                for (int nt = 0; nt < 4; nt++) {
                    mma_bf16(acc[mt][nt], ah[mt], bh[nt]);
                    mma_bf16(acc[mt][nt], ah[mt], bl[nt]);
                    mma_bf16(acc[mt][nt], al[mt], bh[nt]);
                }
        }

        if (c + 1 < nch) {
            __nv_bfloat16* dst = sm + ((c + 1) & 1) * BUF_ELEMS;
            __nv_bfloat16* Ah = dst;
            __nv_bfloat16* Al = dst + MAT_ELEMS;
            __nv_bfloat16* Bh = dst + 2 * MAT_ELEMS;
            __nv_bfloat16* Bl = dst + 3 * MAT_ELEMS;
#pragma unroll
            for (int i = 0; i < 4; i++) {
                const int r = ar0 + i * 32;
                uint2 h, l;
                split2(apre[i].x, apre[i].y, h.x, l.x);
                split2(apre[i].z, apre[i].w, h.y, l.y);
                *(uint2*)&Ah[r * LDR + akq] = h;
                *(uint2*)&Al[r * LDR + akq] = l;
            }
            if (TRANSB) {
#pragma unroll
                for (int i = 0; i < 4; i++) {
                    const int r = ar0 + i * 32;
                    uint2 h, l;
                    split2(bpre[i].x, bpre[i].y, h.x, l.x);
                    split2(bpre[i].z, bpre[i].w, h.y, l.y);
                    *(uint2*)&Bh[r * LDR + akq] = h;
                    *(uint2*)&Bl[r * LDR + akq] = l;
                }
            } else {
#pragma unroll
                for (int i = 0; i < 4; i++) {
                    const int nb = nn4 + i * 32;
                    const float vv[4] = { bpre[i].x, bpre[i].y, bpre[i].z, bpre[i].w };
#pragma unroll
                    for (int j = 0; j < 4; j++) {
                        __nv_bfloat16 hb = __float2bfloat16_rn(vv[j]);
                        float rres = vv[j] - __bfloat162float(hb);
                        Bh[(nb + j) * LDR + nk] = hb;
                        Bl[(nb + j) * LDR + nk] = __float2bfloat16_rn(rres);
                    }
                }
            }
        }
        __syncthreads();
    }

    const int rbase = m0 + wm * 64 + (lane >> 2);
    const int cbase = n0 + wn * 32 + (lane & 3) * 2;
#pragma unroll
    for (int mt = 0; mt < 4; mt++) {
#pragma unroll
        for (int nt = 0; nt < 4; nt++) {
            const int col = cbase + nt * 8;
#pragma unroll
            for (int half = 0; half < 2; half++) {
                const int r = rbase + mt * 16 + half * 8;
                float v0 = acc[mt][nt][half * 2];
                float v1 = acc[mt][nt][half * 2 + 1];
                if (EPI == 1) { v0 = fmaxf(v0, 0.f); v1 = fmaxf(v1, 0.f); }
                else if (EPI == 2) {
                    const float2 e = *(const float2*)&E[(size_t)r * eN + col];
                    v0 *= e.x; v1 *= e.y;
                } else if (EPI == 3) {
                    const float2 e = *(const float2*)&E[col];
                    v0 += e.x; v1 += e.y;
                }
                *(float2*)&C[(size_t)r * ldc + col] = make_float2(v0, v1);
            }
        }
    }
}

// ---------------------------------------------------------------------------
__global__ void softmax_dim1_kernel(float* __restrict__ Mm)
{
    const int idx = blockIdx.x * 256 + threadIdx.x;
    const int b = idx >> 9, c = idx & 511;
    float* p = Mm + (size_t)b * (512 * 512) + c;

    float mx = -1e30f, s = 0.f;
    for (int i = 0; i < 512; i++) {
        const float v = p[(size_t)i * 512];
        const float nm = fmaxf(mx, v);
        s = s * __expf(mx - nm) + __expf(v - nm);
        mx = nm;
    }
    const float inv = 1.f / s;
    for (int i = 0; i < 512; i++) {
        const float v = p[(size_t)i * 512];
        p[(size_t)i * 512] = __expf(v - mx) * inv;
    }
}

__global__ void concat_copy_kernel(const float* __restrict__ x1, float* __restrict__ g)
{
    const int idx = blockIdx.x * 256 + threadIdx.x;
    const int m = idx >> 6;
    const int c4 = (idx & 63) << 2;
    *(float4*)&g[(size_t)m * 512 + c4] = *(const float4*)&x1[(size_t)m * 256 + c4];
}

// ---------------------------------------------------------------------------
// GRU v5: warp-autonomous. 16 clusters x 8 CTAs x 256 thr. Warp w owns
// h = gi*32 + w*4 .. +4. Lane = (i 0..3, ks 0..7): 3 gates x 2 batches over a
// 32-k slice (weights in regs). shfl-xor reduce over ks, lanes ks==0 finalize
// and st.async-broadcast h(t+1) with mbarrier tx credits. No __syncthreads
// in the recurrence loop.
// h smem layout: byte(k,b) = (p&15)*128 + ((p>>4)&7)*16 + b*8 + (k&1)*4, p=k>>1
// => per-iteration warp LDS spans 16 consecutive banks (conflict-free).
// ---------------------------------------------------------------------------
__device__ __forceinline__ u64 pk2(float a, float b) {
    u64 r; asm("mov.b64 %0, {%1, %2};" : "=l"(r) : "f"(a), "f"(b)); return r;
}
__device__ __forceinline__ void fma2(u64& d, u64 a, u64 b) {
    asm("fma.rn.f32x2 %0, %1, %2, %0;" : "+l"(d) : "l"(a), "l"(b));
}
__device__ __forceinline__ float2 unpk(u64 v) {
    float2 f; asm("mov.b64 {%0, %1}, %2;" : "=f"(f.x), "=f"(f.y) : "l"(v)); return f;
}
__device__ __forceinline__ float rcpa(float x) {
    float r; asm("rcp.approx.f32 %0, %1;" : "=f"(r) : "f"(x)); return r;
}
__device__ __forceinline__ float sig_f(float x) {        // 1/(1+e^-x)
    return rcpa(1.f + __expf(-x));
}
__device__ __forceinline__ float tanh_f(float x) {       // 2*sig(2x)-1
    return 2.f * rcpa(1.f + __expf(-2.f * x)) - 1.f;
}

template<int CUR, bool DO_WAIT>
__device__ __forceinline__ void gstep(
    int t, int tid, int ks, int hg, int b0,
    const u64 (&w2)[3][16],
    unsigned char (&hraw)[2][2048],
    u32 mb_cur, u32 parity,
    u32 dst_next,          // local addr of h slot (b=0) in hraw[CUR^1]
    u32 mb_next,           // local addr of mb[CUR^1]
    u32 offb,              // byte offset of own h slot (b=0) within a buffer
    float br, float bz, float bn,
    float (&xc)[6], const float* __restrict__ xp, float* __restrict__ out)
{
    // prefetch xp(t+1) — covers a full step of latency
    float xn6[6];
    if (ks == 0) {
        const int tn = (t + 1 < 512) ? t + 1 : 511;
        const float* q0 = xp + ((size_t)b0 * 512 + tn) * 768 + hg;
        const float* q1 = q0 + (size_t)512 * 768;
        xn6[0] = __ldg(q0); xn6[1] = __ldg(q0 + 256); xn6[2] = __ldg(q0 + 512);
        xn6[3] = __ldg(q1); xn6[4] = __ldg(q1 + 256); xn6[5] = __ldg(q1 + 512);
    }

    if (DO_WAIT) {
        mbar_wait(mb_cur, parity);
        if (tid == 0)   // re-arm for this barrier's next phase
            asm volatile("mbarrier.arrive.expect_tx.shared.b64 _, [%0], %1;"
                         :: "r"(mb_cur), "r"(2048u) : "memory");
    }

    const unsigned char* hb = hraw[CUR];
    u64 a00 = 0, a01 = 0, a10 = 0, a11 = 0, a20 = 0, a21 = 0;
#pragma unroll
    for (int kp = 0; kp < 16; kp++) {
        const u64 ha = *(const u64*)(hb + kp * 128 + ks * 16);
        const u64 hv = *(const u64*)(hb + kp * 128 + ks * 16 + 8);
        fma2(a00, ha, w2[0][kp]); fma2(a01, hv, w2[0][kp]);
        fma2(a10, ha, w2[1][kp]); fma2(a11, hv, w2[1][kp]);
        fma2(a20, ha, w2[2][kp]); fma2(a21, hv, w2[2][kp]);
    }
    float s[6];
    { float2 f = unpk(a00); s[0] = f.x + f.y; }
    { float2 f = unpk(a01); s[1] = f.x + f.y; }
    { float2 f = unpk(a10); s[2] = f.x + f.y; }
    { float2 f = unpk(a11); s[3] = f.x + f.y; }
    { float2 f = unpk(a20); s[4] = f.x + f.y; }
    { float2 f = unpk(a21); s[5] = f.x + f.y; }
#pragma unroll
    for (int d = 1; d < 8; d <<= 1)
#pragma unroll
        for (int j = 0; j < 6; j++)
            s[j] += __shfl_xor_sync(0xffffffffu, s[j], d);

    if (ks == 0) {
#pragma unroll
        for (int b = 0; b < 2; b++) {
            const float hr = s[0 + b] + br;       // s[g*2+b]
            const float hz = s[2 + b] + bz;
            const float hn = s[4 + b] + bn;
            const float r = sig_f(xc[b * 3 + 0] + hr);
            const float z = sig_f(xc[b * 3 + 1] + hz);
            const float n = tanh_f(xc[b * 3 + 2] + r * hn);
            const float hp = *(const float*)(hb + offb + b * 8);
            const float hnew = (1.f - z) * n + z * hp;
            const u32 hbits = __float_as_uint(hnew);
            const u32 ldst = dst_next + b * 8;
#pragma unroll
            for (int rk = 0; rk < 8; rk++) {
                u32 ra, rm;
                asm("mapa.shared::cluster.u32 %0, %1, %2;" : "=r"(ra) : "r"(ldst), "r"(rk));
                asm("mapa.shared::cluster.u32 %0, %1, %2;" : "=r"(rm) : "r"(mb_next), "r"(rk));
                asm volatile(
                    "st.async.shared::cluster.mbarrier::complete_tx::bytes.b32 [%0], %1, [%2];"
                    :: "r"(ra), "r"(hbits), "r"(rm) : "memory");
            }
            out[((size_t)(b0 + b) * 512 + t) * 256 + hg] = hnew;
        }
#pragma unroll
        for (int j = 0; j < 6; j++) xc[j] = xn6[j];
    }
}

__global__ void __launch_bounds__(256, 1) __cluster_dims__(8, 1, 1)
gru_kernel(const float* __restrict__ xp,    // [32*512][768] (x-proj incl. bih)
           const float* __restrict__ whh,   // [768][256]
           const float* __restrict__ bhh,   // [768]
           float* __restrict__ out)         // [32*512][256]
{
    __shared__ __align__(16) unsigned char hraw[2][2048];
    __shared__ __align__(8)  u64 mbars[2];

    const int tid = threadIdx.x;
    u32 gi; asm("mov.u32 %0, %%cluster_ctarank;" : "=r"(gi));
    const int b0 = (blockIdx.x >> 3) * 2;
    const int wid = tid >> 5;
    const int lane = tid & 31;
    const int ii = lane >> 3;
    const int ks = lane & 7;
    const int hg = gi * 32 + wid * 4 + ii;

    // per-lane weights: 3 gates x 32-k slice as f32x2 k-pairs
    u64 w2[3][16];
#pragma unroll
    for (int g = 0; g < 3; g++) {
        const float* wr = whh + (size_t)(g * 256 + hg) * 256 + ks * 32;
#pragma unroll
        for (int kp = 0; kp < 16; kp += 2) {
            float4 v = __ldg((const float4*)(wr + kp * 2));
            w2[g][kp]     = pk2(v.x, v.y);
            w2[g][kp + 1] = pk2(v.z, v.w);
        }
    }
    const float br = __ldg(&bhh[hg]);
    const float bz = __ldg(&bhh[256 + hg]);
    const float bn = __ldg(&bhh[512 + hg]);

    const u32 mb0 = saddr(&mbars[0]);
    const u32 mb1 = saddr(&mbars[1]);
    if (tid == 0) {
        asm volatile("mbarrier.init.shared.b64 [%0], 1;" :: "r"(mb0) : "memory");
        asm volatile("mbarrier.init.shared.b64 [%0], 1;" :: "r"(mb1) : "memory");
        asm volatile("fence.proxy.async.shared::cta;" ::: "memory");
        asm volatile("mbarrier.arrive.expect_tx.shared.b64 _, [%0], %1;"
                     :: "r"(mb0), "r"(2048u) : "memory");
        asm volatile("mbarrier.arrive.expect_tx.shared.b64 _, [%0], %1;"
                     :: "r"(mb1), "r"(2048u) : "memory");
    }
    ((u64*)hraw[0])[tid] = 0ull;   // h(0) = 0 (256 * 8B = 2048B)
    __syncthreads();
    asm volatile("barrier.cluster.arrive.aligned;" ::: "memory");
    asm volatile("barrier.cluster.wait.aligned;" ::: "memory");

    // own h slot byte offset (b=0) within a buffer
    const int p = hg >> 1;
    const u32 offb = (u32)((p & 15) * 128 + ((p >> 4) & 7) * 16 + (hg & 1) * 4);
    const u32 d0 = saddr(hraw[0]) + offb;
    const u32 d1 = saddr(hraw[1]) + offb;

    // xp(0)
    float xc[6] = {0.f, 0.f, 0.f, 0.f, 0.f, 0.f};
    if (ks == 0) {
        const float* q0 = xp + ((size_t)b0 * 512) * 768 + hg;
        const float* q1 = q0 + (size_t)512 * 768;
        xc[0] = __ldg(q0); xc[1] = __ldg(q0 + 256); xc[2] = __ldg(q0 + 512);
        xc[3] = __ldg(q1); xc[4] = __ldg(q1 + 256); xc[5] = __ldg(q1 + 512);
    }

    u32 p0 = 0, p1 = 0;
    // t=0: consume local zeros (no wait); write h(1) -> buf1/mb1
    gstep<0, false>(0, tid, ks, hg, b0, w2, hraw, mb0, 0u, d1, mb1, offb,
                    br, bz, bn, xc, xp, out);
    for (int t = 1; t < 511; t += 2) {
        gstep<1, true>(t, tid, ks, hg, b0, w2, hraw, mb1, p1, d0, mb0, offb,
                       br, bz, bn, xc, xp, out);
        p1 ^= 1u;
        gstep<0, true>(t + 1, tid, ks, hg, b0, w2, hraw, mb0, p0, d1, mb1, offb,
                       br, bz, bn, xc, xp, out);
        p0 ^= 1u;
    }
    gstep<1, true>(511, tid, ks, hg, b0, w2, hraw, mb1, p1, d0, mb0, offb,
                   br, bz, bn, xc, xp, out);
    // drain: absorb h(512) credits (peers may still be storing into us)
    mbar_wait(mb0, p0);
}

// ---------------------------------------------------------------------------
extern "C" void kernel_launch(void* const* d_in, const int* in_sizes, int n_in,
                              void* d_out, int out_size)
{
    const float* x1  = (const float*)d_in[0];
    const float* x2  = (const float*)d_in[1];
    const float* w1  = (const float*)d_in[2];
    const float* w2  = (const float*)d_in[3];
    const float* Dm  = (const float*)d_in[4];
    const float* Wm  = (const float*)d_in[5];
    const float* wih = (const float*)d_in[6];
    const float* whh = (const float*)d_in[7];
    const float* bih = (const float*)d_in[8];
    const float* bhh = (const float*)d_in[9];
    float* out = (float*)d_out;

    float* scratch = nullptr;
    cudaGetSymbolAddress((void**)&scratch, g_scratch);

    float* T1 = scratch + OFF_T1;
    float* A1 = scratch + OFF_A1;
    float* A2 = scratch + OFF_A2;
    float* MM = scratch + OFF_M;
    float* GG = scratch + OFF_G;
    float* XP = scratch + OFF_XP;

    cudaFuncSetAttribute(mma_gemm<1, true>,  cudaFuncAttributeMaxDynamicSharedMemorySize, GEMM_SMEM);
    cudaFuncSetAttribute(mma_gemm<0, false>, cudaFuncAttributeMaxDynamicSharedMemorySize, GEMM_SMEM);
    cudaFuncSetAttribute(mma_gemm<2, true>,  cudaFuncAttributeMaxDynamicSharedMemorySize, GEMM_SMEM);
    cudaFuncSetAttribute(mma_gemm<3, true>,  cudaFuncAttributeMaxDynamicSharedMemorySize, GEMM_SMEM);

    const dim3 blk(256);

    // t1 = relu(x1 @ w1^T)   [16384,256]
    mma_gemm<1, true><<<dim3(2, 128, 1), blk, GEMM_SMEM>>>(
        x1, w1, T1, 256, 256, 256, 256, 0, 0, 0, nullptr, 0);
    // a2 = relu(x2 @ w2^T)
    mma_gemm<1, true><<<dim3(2, 128, 1), blk, GEMM_SMEM>>>(
        x2, w2, A2, 256, 256, 256, 256, 0, 0, 0, nullptr, 0);
    // a1 = t1 @ D
    mma_gemm<0, false><<<dim3(2, 128, 1), blk, GEMM_SMEM>>>(
        T1, Dm, A1, 256, 256, 256, 256, 0, 0, 0, nullptr, 0);
    // M[b] = (a1[b] @ a2[b]^T) * W      [32][512][512]
    mma_gemm<2, true><<<dim3(4, 4, 32), blk, GEMM_SMEM>>>(
        A1, A2, MM, 256, 256, 256, 512,
        (long long)512 * 256, (long long)512 * 256, (long long)512 * 512, Wm, 512);
    // softmax over dim=1
    softmax_dim1_kernel<<<64, 256>>>(MM);
    // g left half <- x1
    concat_copy_kernel<<<4096, 256>>>(x1, GG);
    // ctx[b] = M[b] @ x2[b]  -> g right half
    mma_gemm<0, false><<<dim3(2, 4, 32), blk, GEMM_SMEM>>>(
        MM, x2, GG + 256, 512, 512, 256, 512,
        (long long)512 * 512, (long long)512 * 256, (long long)512 * 512, nullptr, 0);
    // xp = g @ wih^T + bih   [16384][768]
    mma_gemm<3, true><<<dim3(6, 128, 1), blk, GEMM_SMEM>>>(
        GG, wih, XP, 512, 512, 512, 768, 0, 0, 0, bih, 0);
    // GRU recurrence (16 independent 8-CTA clusters, warp-autonomous)
    gru_kernel<<<128, 256>>>(XP, whh, bhh, out);
}

// round 14
// speedup vs baseline: 1.1442x; 1.1442x over previous
#include <cuda_runtime.h>
#include <cuda_bf16.h>
#include <cstdint>

typedef unsigned long long u64;
typedef unsigned int u32;

// ---------------------------------------------------------------------------
// EnrichAttention: bf16x3-split HMMA GEMMs (512-thr, 16 warps) -> softmax ->
// ctx -> concat -> GRU v4 (cluster st.async recurrence, reverted from v5).
// ---------------------------------------------------------------------------

// scratch layout (floats)
#define OFF_T1 0
#define OFF_A1 4194304      // 16384*256
#define OFF_A2 8388608
#define OFF_M  12582912     // 32*512*512 = 8388608 floats
#define OFF_G  20971520     // 16384*512  = 8388608
#define OFF_XP 29360128     // 16384*768  = 12582912
#define SCRATCH_FLOATS 41943040

__device__ float g_scratch[SCRATCH_FLOATS];

// ---- helpers ----------------------------------------------------------------
__device__ __forceinline__ u32 saddr(const void* p) {
    u32 a;
    asm("{ .reg .u64 t; cvta.to.shared.u64 t, %1; cvt.u32.u64 %0, t; }"
        : "=r"(a) : "l"(p));
    return a;
}
__device__ __forceinline__ void mbar_wait(u32 mbar, u32 parity) {
    u32 done;
    asm volatile(
        "{\n\t.reg .pred p;\n\t"
        "mbarrier.try_wait.parity.acquire.cta.shared::cta.b64 p, [%1], %2;\n\t"
        "selp.b32 %0, 1, 0, p;\n\t}"
        : "=r"(done) : "r"(mbar), "r"(parity) : "memory");
    if (!done) {
        asm volatile(
            "{\n\t.reg .pred P1;\n\t"
            "WL%=:\n\t"
            "mbarrier.try_wait.parity.acquire.cta.shared::cta.b64 P1, [%0], %1, 0x989680;\n\t"
            "@P1 bra.uni WD%=;\n\t"
            "bra.uni WL%=;\n\t"
            "WD%=:\n\t}"
            :: "r"(mbar), "r"(parity) : "memory");
    }
}

// ---------------------------------------------------------------------------
// bf16x3 HMMA GEMM. CTA tile 128x128, K-tile 32, 512 threads = 16 warps (4x4),
// warp tile 32x32 (regs ~100 -> 16 warps/SM, 2x latency cover vs R12).
// Split: x = hi(bf16) + lo(bf16); acc += Ah*Bh + Ah*Bl + Al*Bh (fp32 acc).
// EPI: 0=none, 1=relu, 2=mul by E[r*eN+c], 3=add bias E[c]
// TRANSB: true -> B is [N,K] (C=A*B^T); false -> B is [K,N] (C=A*B)
// ---------------------------------------------------------------------------
#define LDR 40
#define MAT_ELEMS (128 * LDR)
#define BUF_ELEMS (4 * MAT_ELEMS)
#define GEMM_SMEM (2 * BUF_ELEMS * 2)   // 81920 B

__device__ __forceinline__ void split2(float x, float y, u32& hi, u32& lo) {
    __nv_bfloat16 hx = __float2bfloat16_rn(x), hy = __float2bfloat16_rn(y);
    float rx = x - __bfloat162float(hx), ry = y - __bfloat162float(hy);
    __nv_bfloat16 lx = __float2bfloat16_rn(rx), ly = __float2bfloat16_rn(ry);
    hi = ((u32)__bfloat16_as_ushort(hy) << 16) | __bfloat16_as_ushort(hx);
    lo = ((u32)__bfloat16_as_ushort(ly) << 16) | __bfloat16_as_ushort(lx);
}
__device__ __forceinline__ void ldsm4(u32& r0, u32& r1, u32& r2, u32& r3, u32 a) {
    asm volatile("ldmatrix.sync.aligned.m8n8.x4.shared.b16 {%0,%1,%2,%3}, [%4];"
                 : "=r"(r0), "=r"(r1), "=r"(r2), "=r"(r3) : "r"(a));
}
__device__ __forceinline__ void mma_bf16(float* c, const u32* a, const u32* b) {
    asm volatile(
        "mma.sync.aligned.m16n8k16.row.col.f32.bf16.bf16.f32 "
        "{%0,%1,%2,%3}, {%4,%5,%6,%7}, {%8,%9}, {%0,%1,%2,%3};"
        : "+f"(c[0]), "+f"(c[1]), "+f"(c[2]), "+f"(c[3])
        : "r"(a[0]), "r"(a[1]), "r"(a[2]), "r"(a[3]), "r"(b[0]), "r"(b[1]));
}

template<int EPI, bool TRANSB>
__global__ void __launch_bounds__(512) mma_gemm(
    const float* __restrict__ A, const float* __restrict__ B,
    float* __restrict__ C, int K, int lda, int ldb, int ldc,
    long long sA, long long sB, long long sC,
    const float* __restrict__ E, int eN)
{
    extern __shared__ __align__(16) __nv_bfloat16 sm[];
    A += (size_t)blockIdx.z * sA;
    B += (size_t)blockIdx.z * sB;
    C += (size_t)blockIdx.z * sC;

    const int tid = threadIdx.x;
    const int wid = tid >> 5, lane = tid & 31;
    const int wm = wid >> 2, wn = wid & 3;           // 4x4 warp grid
    const int m0 = blockIdx.y * 128, n0 = blockIdx.x * 128;

    // loader indices (512 threads)
    const int ar0 = tid >> 3;             // 0..63 row, +64 per iter (2 iters)
    const int akq = (tid & 7) * 4;        // k quad
    const int nk  = tid & 31;             // NN loader: k
    const int nn4 = (tid >> 5) * 4;       // NN loader: n quad 0..60, +64/iter

    // ldmatrix per-thread tile offsets (bf16 elems)
    const int q = lane >> 3, lr = lane & 7;
    const int a_t = (lr + (q & 1) * 8) * LDR + (q >> 1) * 8;
    const int b_t = (lr + (q >> 1) * 8) * LDR + (q & 1) * 8;
    const u32 smb = saddr(sm);

    float acc[2][4][4];
#pragma unroll
    for (int mt = 0; mt < 2; mt++)
#pragma unroll
        for (int nt = 0; nt < 4; nt++)
#pragma unroll
            for (int e = 0; e < 4; e++) acc[mt][nt][e] = 0.f;

    const int nch = K >> 5;

    // ---- prologue: chunk 0 -> buffer 0 ----
    {
        __nv_bfloat16* Ah = sm;
        __nv_bfloat16* Al = sm + MAT_ELEMS;
        __nv_bfloat16* Bh = sm + 2 * MAT_ELEMS;
        __nv_bfloat16* Bl = sm + 3 * MAT_ELEMS;
#pragma unroll
        for (int i = 0; i < 2; i++) {
            const int r = ar0 + i * 64;
            float4 v = *(const float4*)(A + (size_t)(m0 + r) * lda + akq);
            uint2 h, l;
            split2(v.x, v.y, h.x, l.x); split2(v.z, v.w, h.y, l.y);
            *(uint2*)&Ah[r * LDR + akq] = h;
            *(uint2*)&Al[r * LDR + akq] = l;
        }
        if (TRANSB) {
#pragma unroll
            for (int i = 0; i < 2; i++) {
                const int r = ar0 + i * 64;
                float4 v = *(const float4*)(B + (size_t)(n0 + r) * ldb + akq);
                uint2 h, l;
                split2(v.x, v.y, h.x, l.x); split2(v.z, v.w, h.y, l.y);
                *(uint2*)&Bh[r * LDR + akq] = h;
                *(uint2*)&Bl[r * LDR + akq] = l;
            }
        } else {
#pragma unroll
            for (int i = 0; i < 2; i++) {
                const int nb = nn4 + i * 64;
                float4 v = *(const float4*)(B + (size_t)nk * ldb + n0 + nb);
                const float vv[4] = { v.x, v.y, v.z, v.w };
#pragma unroll
                for (int j = 0; j < 4; j++) {
                    __nv_bfloat16 hb = __float2bfloat16_rn(vv[j]);
                    float rres = vv[j] - __bfloat162float(hb);
                    Bh[(nb + j) * LDR + nk] = hb;
                    Bl[(nb + j) * LDR + nk] = __float2bfloat16_rn(rres);
                }
            }
        }
    }
    __syncthreads();

    for (int c = 0; c < nch; c++) {
        const int buf = c & 1;
        const u32 base = smb + buf * (BUF_ELEMS * 2);

        // prefetch chunk c+1 into registers
        float4 apre[2], bpre[2];
        if (c + 1 < nch) {
            const int k0 = (c + 1) * 32;
#pragma unroll
            for (int i = 0; i < 2; i++)
                apre[i] = *(const float4*)(A + (size_t)(m0 + ar0 + i * 64) * lda + k0 + akq);
            if (TRANSB) {
#pragma unroll
                for (int i = 0; i < 2; i++)
                    bpre[i] = *(const float4*)(B + (size_t)(n0 + ar0 + i * 64) * ldb + k0 + akq);
            } else {
#pragma unroll
                for (int i = 0; i < 2; i++)
                    bpre[i] = *(const float4*)(B + (size_t)(k0 + nk) * ldb + n0 + nn4 + i * 64);
            }
        }

        // ---- MMA on buffer buf: 2 k-steps of 16 ----
#pragma unroll
        for (int ks = 0; ks < 32; ks += 16) {
            u32 ah[2][4], al[2][4], bh[4][2], bl[4][2];
#pragma unroll
            for (int mt = 0; mt < 2; mt++) {
                const u32 off = (u32)(a_t + (wm * 32 + mt * 16) * LDR + ks) * 2;
                ldsm4(ah[mt][0], ah[mt][1], ah[mt][2], ah[mt][3], base + off);
                ldsm4(al[mt][0], al[mt][1], al[mt][2], al[mt][3],
                      base + off + MAT_ELEMS * 2);
            }
#pragma unroll
            for (int np = 0; np < 2; np++) {
                const u32 off = (u32)(b_t + (wn * 32 + np * 16) * LDR + ks) * 2;
                u32 t0, t1, t2, t3;
                ldsm4(t0, t1, t2, t3, base + off + 2 * MAT_ELEMS * 2);
                bh[2 * np][0] = t0; bh[2 * np][1] = t1;
                bh[2 * np + 1][0] = t2; bh[2 * np + 1][1] = t3;
                ldsm4(t0, t1, t2, t3, base + off + 3 * MAT_ELEMS * 2);
                bl[2 * np][0] = t0; bl[2 * np][1] = t1;
                bl[2 * np + 1][0] = t2; bl[2 * np + 1][1] = t3;
            }
#pragma unroll
            for (int mt = 0; mt < 2; mt++)
#pragma unroll
                for (int nt = 0; nt < 4; nt++) {
                    mma_bf16(acc[mt][nt], ah[mt], bh[nt]);
                    mma_bf16(acc[mt][nt], ah[mt], bl[nt]);
                    mma_bf16(acc[mt][nt], al[mt], bh[nt]);
                }
        }

        // ---- store prefetched chunk into the other buffer ----
        if (c + 1 < nch) {
            __nv_bfloat16* dst = sm + ((c + 1) & 1) * BUF_ELEMS;
            __nv_bfloat16* Ah = dst;
            __nv_bfloat16* Al = dst + MAT_ELEMS;
            __nv_bfloat16* Bh = dst + 2 * MAT_ELEMS;
            __nv_bfloat16* Bl = dst + 3 * MAT_ELEMS;
#pragma unroll
            for (int i = 0; i < 2; i++) {
                const int r = ar0 + i * 64;
                uint2 h, l;
                split2(apre[i].x, apre[i].y, h.x, l.x);
                split2(apre[i].z, apre[i].w, h.y, l.y);
                *(uint2*)&Ah[r * LDR + akq] = h;
                *(uint2*)&Al[r * LDR + akq] = l;
            }
            if (TRANSB) {
#pragma unroll
                for (int i = 0; i < 2; i++) {
                    const int r = ar0 + i * 64;
                    uint2 h, l;
                    split2(bpre[i].x, bpre[i].y, h.x, l.x);
                    split2(bpre[i].z, bpre[i].w, h.y, l.y);
                    *(uint2*)&Bh[r * LDR + akq] = h;
                    *(uint2*)&Bl[r * LDR + akq] = l;
                }
            } else {
#pragma unroll
                for (int i = 0; i < 2; i++) {
                    const int nb = nn4 + i * 64;
                    const float vv[4] = { bpre[i].x, bpre[i].y, bpre[i].z, bpre[i].w };
#pragma unroll
                    for (int j = 0; j < 4; j++) {
                        __nv_bfloat16 hb = __float2bfloat16_rn(vv[j]);
                        float rres = vv[j] - __bfloat162float(hb);
                        Bh[(nb + j) * LDR + nk] = hb;
                        Bl[(nb + j) * LDR + nk] = __float2bfloat16_rn(rres);
                    }
                }
            }
        }
        __syncthreads();
    }

    // ---- epilogue ----
    const int rbase = m0 + wm * 32 + (lane >> 2);
    const int cbase = n0 + wn * 32 + (lane & 3) * 2;
#pragma unroll
    for (int mt = 0; mt < 2; mt++) {
#pragma unroll
        for (int nt = 0; nt < 4; nt++) {
            const int col = cbase + nt * 8;
#pragma unroll
            for (int half = 0; half < 2; half++) {
                const int r = rbase + mt * 16 + half * 8;
                float v0 = acc[mt][nt][half * 2];
                float v1 = acc[mt][nt][half * 2 + 1];
                if (EPI == 1) { v0 = fmaxf(v0, 0.f); v1 = fmaxf(v1, 0.f); }
                else if (EPI == 2) {
                    const float2 e = *(const float2*)&E[(size_t)r * eN + col];
                    v0 *= e.x; v1 *= e.y;
                } else if (EPI == 3) {
                    const float2 e = *(const float2*)&E[col];
                    v0 += e.x; v1 += e.y;
                }
                *(float2*)&C[(size_t)r * ldc + col] = make_float2(v0, v1);
            }
        }
    }
}

// ---------------------------------------------------------------------------
__global__ void softmax_dim1_kernel(float* __restrict__ Mm)
{
    const int idx = blockIdx.x * 256 + threadIdx.x;
    const int b = idx >> 9, c = idx & 511;
    float* p = Mm + (size_t)b * (512 * 512) + c;

    float mx = -1e30f, s = 0.f;
    for (int i = 0; i < 512; i++) {
        const float v = p[(size_t)i * 512];
        const float nm = fmaxf(mx, v);
        s = s * __expf(mx - nm) + __expf(v - nm);
        mx = nm;
    }
    const float inv = 1.f / s;
    for (int i = 0; i < 512; i++) {
        const float v = p[(size_t)i * 512];
        p[(size_t)i * 512] = __expf(v - mx) * inv;
    }
}

__global__ void concat_copy_kernel(const float* __restrict__ x1, float* __restrict__ g)
{
    const int idx = blockIdx.x * 256 + threadIdx.x;
    const int m = idx >> 6;
    const int c4 = (idx & 63) << 2;
    *(float4*)&g[(size_t)m * 512 + c4] = *(const float4*)&x1[(size_t)m * 256 + c4];
}

// ---------------------------------------------------------------------------
// GRU v4 (reverted — the measured-best recurrence): 16 clusters of 8 CTAs,
// st.async data-driven sync, smem partials reduce, 64-thread finalize.
// ---------------------------------------------------------------------------
__device__ __forceinline__ u64 pk2(float a, float b) {
    u64 r; asm("mov.b64 %0, {%1, %2};" : "=l"(r) : "f"(a), "f"(b)); return r;
}
__device__ __forceinline__ void fma2(u64& d, u64 a, u64 b) {
    asm("fma.rn.f32x2 %0, %1, %2, %0;" : "+l"(d) : "l"(a), "l"(b));
}
__device__ __forceinline__ u64 add2(u64 a, u64 b) {
    u64 d; asm("add.rn.f32x2 %0, %1, %2;" : "=l"(d) : "l"(a), "l"(b)); return d;
}
__device__ __forceinline__ float2 unpk(u64 v) {
    float2 f; asm("mov.b64 {%0, %1}, %2;" : "=f"(f.x), "=f"(f.y) : "l"(v)); return f;
}

template<int CUR, bool DO_WAIT>
__device__ __forceinline__ void gru_step(
    int t, int tid, int kq, int b0, int gi, int b_l, int hl2,
    const u64 (&w2reg)[3][16],
    u64 (&hbuf)[2][2][128], u64 (&parts)[3][2][8][32],
    u32 mb_cur, u32 parity,
    const u32 (&dd)[8], const u32 (&dm)[8],
    float br, float bz, float bn,
    float& xr_c, float& xz_c, float& xn_c,
    const float* __restrict__ xp, float* __restrict__ out)
{
    float xr_n = 0.f, xz_n = 0.f, xn_n = 0.f;
    if (tid < 64) {
        const int tn = (t + 1 < 512) ? t + 1 : 511;
        const float* p = xp + ((size_t)(b0 + b_l) * 512 + tn) * 768 + gi * 32 + hl2;
        xr_n = __ldg(p); xz_n = __ldg(p + 256); xn_n = __ldg(p + 512);
    }

    if (DO_WAIT) {
        mbar_wait(mb_cur, parity);
        if (tid == 0)
            asm volatile("mbarrier.arrive.expect_tx.shared.b64 _, [%0], %1;"
                         :: "r"(mb_cur), "r"(2048u) : "memory");
    }

    const int h_l = tid & 31;
    const u64* h0p = &hbuf[CUR][0][kq * 16];
    const u64* h1p = &hbuf[CUR][1][kq * 16];
    u64 a00 = 0, a01 = 0, a10 = 0, a11 = 0, a20 = 0, a21 = 0;
#pragma unroll
    for (int kp = 0; kp < 16; kp++) {
        const u64 ha = h0p[kp], hb = h1p[kp];
        fma2(a00, ha, w2reg[0][kp]); fma2(a01, hb, w2reg[0][kp]);
        fma2(a10, ha, w2reg[1][kp]); fma2(a11, hb, w2reg[1][kp]);
        fma2(a20, ha, w2reg[2][kp]); fma2(a21, hb, w2reg[2][kp]);
    }
    parts[0][0][kq][h_l] = a00; parts[0][1][kq][h_l] = a01;
    parts[1][0][kq][h_l] = a10; parts[1][1][kq][h_l] = a11;
    parts[2][0][kq][h_l] = a20; parts[2][1][kq][h_l] = a21;
    __syncthreads();

    if (tid < 64) {
        u64 sr = parts[0][b_l][0][hl2];
        u64 sz = parts[1][b_l][0][hl2];
        u64 sn = parts[2][b_l][0][hl2];
#pragma unroll
        for (int qq = 1; qq < 8; qq++) {
            sr = add2(sr, parts[0][b_l][qq][hl2]);
            sz = add2(sz, parts[1][b_l][qq][hl2]);
            sn = add2(sn, parts[2][b_l][qq][hl2]);
        }
        const float2 fr = unpk(sr), fz = unpk(sz), fn = unpk(sn);
        const float hr = fr.x + fr.y + br;
        const float hz = fz.x + fz.y + bz;
        const float hn = fn.x + fn.y + bn;

        const float r = 1.f / (1.f + __expf(-(xr_c + hr)));
        const float z = 1.f / (1.f + __expf(-(xz_c + hz)));
        const float n = tanhf(xn_c + r * hn);
        const float hp = ((const float*)&hbuf[CUR][b_l][0])[gi * 32 + hl2];
        const float hnew = (1.f - z) * n + z * hp;
        const u32 hbits = __float_as_uint(hnew);

#pragma unroll
        for (int rk = 0; rk < 8; rk++)
            asm volatile(
                "st.async.shared::cluster.mbarrier::complete_tx::bytes.b32 [%0], %1, [%2];"
                :: "r"(dd[rk]), "r"(hbits), "r"(dm[rk]) : "memory");

        out[((size_t)(b0 + b_l) * 512 + t) * 256 + gi * 32 + hl2] = hnew;
    }
    xr_c = xr_n; xz_c = xz_n; xn_c = xn_n;
}

__global__ void __launch_bounds__(256, 1) __cluster_dims__(8, 1, 1)
gru_kernel(const float* __restrict__ xp,
           const float* __restrict__ whh,
           const float* __restrict__ bhh,
           float* __restrict__ out)
{
    __shared__ __align__(16) u64 hbuf[2][2][128];
    __shared__ __align__(16) u64 parts[3][2][8][32];
    __shared__ __align__(8)  u64 mbars[2];

    const int tid = threadIdx.x;
    u32 gi; asm("mov.u32 %0, %%cluster_ctarank;" : "=r"(gi));
    const int b0 = (blockIdx.x >> 3) * 2;
    const int h_l = tid & 31;
    const int kq  = tid >> 5;
    const int hg  = gi * 32 + h_l;

    u64 w2reg[3][16];
#pragma unroll
    for (int g = 0; g < 3; g++) {
        const float* wr = whh + (size_t)(g * 256 + hg) * 256 + kq * 32;
#pragma unroll
        for (int kp = 0; kp < 16; kp += 2) {
            float4 v = __ldg((const float4*)(wr + kp * 2));
            w2reg[g][kp]     = pk2(v.x, v.y);
            w2reg[g][kp + 1] = pk2(v.z, v.w);
        }
    }

    const u32 mb0 = saddr(&mbars[0]);
    const u32 mb1 = saddr(&mbars[1]);
    if (tid == 0) {
        asm volatile("mbarrier.init.shared.b64 [%0], 1;" :: "r"(mb0) : "memory");
        asm volatile("mbarrier.init.shared.b64 [%0], 1;" :: "r"(mb1) : "memory");
        asm volatile("fence.proxy.async.shared::cta;" ::: "memory");
        asm volatile("mbarrier.arrive.expect_tx.shared.b64 _, [%0], %1;"
                     :: "r"(mb0), "r"(2048u) : "memory");
        asm volatile("mbarrier.arrive.expect_tx.shared.b64 _, [%0], %1;"
                     :: "r"(mb1), "r"(2048u) : "memory");
    }
    ((u64*)hbuf)[tid] = 0ull;
    ((u64*)hbuf)[tid + 256] = 0ull;
    __syncthreads();
    asm volatile("barrier.cluster.arrive.aligned;" ::: "memory");
    asm volatile("barrier.cluster.wait.aligned;" ::: "memory");

    float br = 0.f, bz = 0.f, bn = 0.f;
    int b_l = 0, hl2 = 0;
    u32 dd0[8], dd1[8], dm0[8], dm1[8];
#pragma unroll
    for (int rk = 0; rk < 8; rk++) { dd0[rk] = dd1[rk] = dm0[rk] = dm1[rk] = 0u; }
    if (tid < 64) {
        b_l = tid >> 5; hl2 = tid & 31;
        const int hgf = gi * 32 + hl2;
        br = __ldg(&bhh[hgf]);
        bz = __ldg(&bhh[256 + hgf]);
        bn = __ldg(&bhh[512 + hgf]);
        const u32 la0 = saddr(&((float*)&hbuf[0][b_l][0])[hgf]);
        const u32 la1 = saddr(&((float*)&hbuf[1][b_l][0])[hgf]);
#pragma unroll
        for (int rk = 0; rk < 8; rk++) {
            asm("mapa.shared::cluster.u32 %0, %1, %2;" : "=r"(dd0[rk]) : "r"(la0), "r"(rk));
            asm("mapa.shared::cluster.u32 %0, %1, %2;" : "=r"(dd1[rk]) : "r"(la1), "r"(rk));
            asm("mapa.shared::cluster.u32 %0, %1, %2;" : "=r"(dm0[rk]) : "r"(mb0), "r"(rk));
            asm("mapa.shared::cluster.u32 %0, %1, %2;" : "=r"(dm1[rk]) : "r"(mb1), "r"(rk));
        }
    }

    float xr_c = 0.f, xz_c = 0.f, xn_c = 0.f;
    if (tid < 64) {
        const float* p = xp + ((size_t)(b0 + b_l) * 512) * 768 + gi * 32 + hl2;
        xr_c = __ldg(p); xz_c = __ldg(p + 256); xn_c = __ldg(p + 512);
    }

    u32 p0 = 0, p1 = 0;
    gru_step<0, false>(0, tid, kq, b0, gi, b_l, hl2, w2reg, hbuf, parts,
                       mb0, 0u, dd1, dm1, br, bz, bn, xr_c, xz_c, xn_c, xp, out);
    for (int t = 1; t < 511; t += 2) {
        gru_step<1, true>(t, tid, kq, b0, gi, b_l, hl2, w2reg, hbuf, parts,
                          mb1, p1, dd0, dm0, br, bz, bn, xr_c, xz_c, xn_c, xp, out);
        p1 ^= 1u;
        gru_step<0, true>(t + 1, tid, kq, b0, gi, b_l, hl2, w2reg, hbuf, parts,
                          mb0, p0, dd1, dm1, br, bz, bn, xr_c, xz_c, xn_c, xp, out);
        p0 ^= 1u;
    }
    gru_step<1, true>(511, tid, kq, b0, gi, b_l, hl2, w2reg, hbuf, parts,
                      mb1, p1, dd0, dm0, br, bz, bn, xr_c, xz_c, xn_c, xp, out);
    mbar_wait(mb0, p0);
}

// ---------------------------------------------------------------------------
extern "C" void kernel_launch(void* const* d_in, const int* in_sizes, int n_in,
                              void* d_out, int out_size)
{
    const float* x1  = (const float*)d_in[0];
    const float* x2  = (const float*)d_in[1];
    const float* w1  = (const float*)d_in[2];
    const float* w2  = (const float*)d_in[3];
    const float* Dm  = (const float*)d_in[4];
    const float* Wm  = (const float*)d_in[5];
    const float* wih = (const float*)d_in[6];
    const float* whh = (const float*)d_in[7];
    const float* bih = (const float*)d_in[8];
    const float* bhh = (const float*)d_in[9];
    float* out = (float*)d_out;

    float* scratch = nullptr;
    cudaGetSymbolAddress((void**)&scratch, g_scratch);

    float* T1 = scratch + OFF_T1;
    float* A1 = scratch + OFF_A1;
    float* A2 = scratch + OFF_A2;
    float* MM = scratch + OFF_M;
    float* GG = scratch + OFF_G;
    float* XP = scratch + OFF_XP;

    cudaFuncSetAttribute(mma_gemm<1, true>,  cudaFuncAttributeMaxDynamicSharedMemorySize, GEMM_SMEM);
    cudaFuncSetAttribute(mma_gemm<0, false>, cudaFuncAttributeMaxDynamicSharedMemorySize, GEMM_SMEM);
    cudaFuncSetAttribute(mma_gemm<2, true>,  cudaFuncAttributeMaxDynamicSharedMemorySize, GEMM_SMEM);
    cudaFuncSetAttribute(mma_gemm<3, true>,  cudaFuncAttributeMaxDynamicSharedMemorySize, GEMM_SMEM);

    const dim3 blk(512);

    // t1 = relu(x1 @ w1^T)   [16384,256]
    mma_gemm<1, true><<<dim3(2, 128, 1), blk, GEMM_SMEM>>>(
        x1, w1, T1, 256, 256, 256, 256, 0, 0, 0, nullptr, 0);
    // a2 = relu(x2 @ w2^T)
    mma_gemm<1, true><<<dim3(2, 128, 1), blk, GEMM_SMEM>>>(
        x2, w2, A2, 256, 256, 256, 256, 0, 0, 0, nullptr, 0);
    // a1 = t1 @ D
    mma_gemm<0, false><<<dim3(2, 128, 1), blk, GEMM_SMEM>>>(
        T1, Dm, A1, 256, 256, 256, 256, 0, 0, 0, nullptr, 0);
    // M[b] = (a1[b] @ a2[b]^T) * W      [32][512][512]
    mma_gemm<2, true><<<dim3(4, 4, 32), blk, GEMM_SMEM>>>(
        A1, A2, MM, 256, 256, 256, 512,
        (long long)512 * 256, (long long)512 * 256, (long long)512 * 512, Wm, 512);
    // softmax over dim=1
    softmax_dim1_kernel<<<64, 256>>>(MM);
    // g left half <- x1
    concat_copy_kernel<<<4096, 256>>>(x1, GG);
    // ctx[b] = M[b] @ x2[b]  -> g right half
    mma_gemm<0, false><<<dim3(2, 4, 32), blk, GEMM_SMEM>>>(
        MM, x2, GG + 256, 512, 512, 256, 512,
        (long long)512 * 512, (long long)512 * 256, (long long)512 * 512, nullptr, 0);
    // xp = g @ wih^T + bih   [16384][768]
    mma_gemm<3, true><<<dim3(6, 128, 1), blk, GEMM_SMEM>>>(
        GG, wih, XP, 512, 512, 512, 768, 0, 0, 0, bih, 0);
    // GRU recurrence (16 independent 8-CTA clusters, data-driven sync)
    gru_kernel<<<128, 256>>>(XP, whh, bhh, out);
}

// round 15
// speedup vs baseline: 1.1552x; 1.0096x over previous
#include <cuda_runtime.h>
#include <cuda_bf16.h>
#include <cstdint>

typedef unsigned long long u64;
typedef unsigned int u32;
typedef __nv_bfloat16 bf16;

// ---------------------------------------------------------------------------
// EnrichAttention. All GEMMs consume PRE-SPLIT bf16 hi/lo operands via a
// 4-stage cp.async pipeline (TRANSB form only). fp32 exists only where needed
// (scores for softmax, xp for GRU). GRU v4 unchanged.
// ---------------------------------------------------------------------------

// fp32 scratch: MM [32][512][512] at 0; XP [16384][768] at 8388608
#define F_MM 0
#define F_XP 8388608
__device__ float g_f32[20971520];

// bf16 scratch offsets (elements)
#define O_GGH   0           // [16384][512] (left=x1 split, right=ctx split)
#define O_GGL   8388608
#define O_X2H   16777216    // [16384][256]
#define O_X2L   20971520
#define O_X2TH  25165824    // [32][256][512] per-batch transpose
#define O_X2TL  29360128
#define O_T1H   33554432    // [16384][256]
#define O_T1L   37748736
#define O_A1H   41943040
#define O_A1L   46137344
#define O_A2H   50331648
#define O_A2L   54525952
#define O_MH    58720256    // [32][512][512]
#define O_ML    67108864
#define O_W1H   75497472    // [256][256]
#define O_W1L   75563008
#define O_W2H   75628544
#define O_W2L   75694080
#define O_DTH   75759616    // D^T [256][256]
#define O_DTL   75825152
#define O_WIHH  75890688    // [768][512]
#define O_WIHL  76283904
__device__ bf16 g_bf[76677120];

// ---- helpers ----------------------------------------------------------------
__device__ __forceinline__ u32 saddr(const void* p) {
    u32 a;
    asm("{ .reg .u64 t; cvta.to.shared.u64 t, %1; cvt.u32.u64 %0, t; }"
        : "=r"(a) : "l"(p));
    return a;
}
__device__ __forceinline__ void mbar_wait(u32 mbar, u32 parity) {
    u32 done;
    asm volatile(
        "{\n\t.reg .pred p;\n\t"
        "mbarrier.try_wait.parity.acquire.cta.shared::cta.b64 p, [%1], %2;\n\t"
        "selp.b32 %0, 1, 0, p;\n\t}"
        : "=r"(done) : "r"(mbar), "r"(parity) : "memory");
    if (!done) {
        asm volatile(
            "{\n\t.reg .pred P1;\n\t"
            "WL%=:\n\t"
            "mbarrier.try_wait.parity.acquire.cta.shared::cta.b64 P1, [%0], %1, 0x989680;\n\t"
            "@P1 bra.uni WD%=;\n\t"
            "bra.uni WL%=;\n\t"
            "WD%=:\n\t}"
            :: "r"(mbar), "r"(parity) : "memory");
    }
}
__device__ __forceinline__ void cp16(u32 smem, const void* g) {
    asm volatile("cp.async.cg.shared.global [%0], [%1], 16;"
                 :: "r"(smem), "l"(g) : "memory");
}
__device__ __forceinline__ void split1(float v, bf16& h, bf16& l) {
    h = __float2bfloat16_rn(v);
    l = __float2bfloat16_rn(v - __bfloat162float(h));
}

// ---------------------------------------------------------------------------
// Conversion kernels
// ---------------------------------------------------------------------------
// fp32 [rows][src_ld] -> bf16 hi/lo [rows][dst_ld]; cols = 4 << (shift-2)... :
// idx covers rows*(cols/4); shift = log2(cols/4).
__global__ void conv_split(const float* __restrict__ src,
                           bf16* __restrict__ dh, bf16* __restrict__ dl,
                           int src_ld, int dst_ld, int shift, int total)
{
    const int idx = blockIdx.x * 256 + threadIdx.x;
    if (idx >= total) return;
    const int row = idx >> shift;
    const int c4 = (idx & ((1 << shift) - 1)) << 2;
    float4 v = *(const float4*)(src + (size_t)row * src_ld + c4);
    bf16 h0, l0, h1, l1, h2, l2, h3, l3;
    split1(v.x, h0, l0); split1(v.y, h1, l1);
    split1(v.z, h2, l2); split1(v.w, h3, l3);
    u32 hA = ((u32)__bfloat16_as_ushort(h1) << 16) | __bfloat16_as_ushort(h0);
    u32 hB = ((u32)__bfloat16_as_ushort(h3) << 16) | __bfloat16_as_ushort(h2);
    u32 lA = ((u32)__bfloat16_as_ushort(l1) << 16) | __bfloat16_as_ushort(l0);
    u32 lB = ((u32)__bfloat16_as_ushort(l3) << 16) | __bfloat16_as_ushort(l2);
    *(uint2*)(dh + (size_t)row * dst_ld + c4) = make_uint2(hA, hB);
    *(uint2*)(dl + (size_t)row * dst_ld + c4) = make_uint2(lA, lB);
}

// fp32 [z][R][C] -> bf16 split [z][C][R] (transpose within batch)
__global__ void conv_trans(const float* __restrict__ src,
                           bf16* __restrict__ dh, bf16* __restrict__ dl,
                           int R, int C, long long ss, long long sd)
{
    __shared__ float t[32][33];
    const int z = blockIdx.z;
    src += (size_t)z * ss; dh += (size_t)z * sd; dl += (size_t)z * sd;
    const int c0 = blockIdx.x * 32, r0 = blockIdx.y * 32;
    const int tx = threadIdx.x, ty = threadIdx.y;
#pragma unroll
    for (int i = 0; i < 4; i++)
        t[ty + i * 8][tx] = src[(size_t)(r0 + ty + i * 8) * C + c0 + tx];
    __syncthreads();
#pragma unroll
    for (int i = 0; i < 4; i++) {
        const float v = t[tx][ty + i * 8];
        bf16 h, l; split1(v, h, l);
        const size_t o = (size_t)(c0 + ty + i * 8) * R + r0 + tx;
        dh[o] = h; dl[o] = l;
    }
}

// ---------------------------------------------------------------------------
// Unified bf16x3 HMMA GEMM, pre-split operands, 4-stage cp.async pipeline.
// CTA 128x128, K-chunk 32, 512 threads = 16 warps (4x4), warp tile 32x32.
// All GEMMs are TRANSB (B rows = N, k-contiguous).
// EPI: 0=none, 1=relu, 2=mul E[r*eN+c], 3=add E[c]
// OUT: 0 = fp32 C; 1 = split bf16 Ch/Cl
// ---------------------------------------------------------------------------
#define LDR 40
#define MATB 10240                 // 128*40*2 bytes per matrix
#define STGB (4 * MATB)            // 40960 per stage
#define GEMM_SMEM (4 * STGB)       // 163840 (4 stages)

__device__ __forceinline__ void ldsm4(u32& r0, u32& r1, u32& r2, u32& r3, u32 a) {
    asm volatile("ldmatrix.sync.aligned.m8n8.x4.shared.b16 {%0,%1,%2,%3}, [%4];"
                 : "=r"(r0), "=r"(r1), "=r"(r2), "=r"(r3) : "r"(a));
}
__device__ __forceinline__ void mma_bf16(float* c, const u32* a, const u32* b) {
    asm volatile(
        "mma.sync.aligned.m16n8k16.row.col.f32.bf16.bf16.f32 "
        "{%0,%1,%2,%3}, {%4,%5,%6,%7}, {%8,%9}, {%0,%1,%2,%3};"
        : "+f"(c[0]), "+f"(c[1]), "+f"(c[2]), "+f"(c[3])
        : "r"(a[0]), "r"(a[1]), "r"(a[2]), "r"(a[3]), "r"(b[0]), "r"(b[1]));
}

template<int EPI, int OUT>
__global__ void __launch_bounds__(512) gemm_bb(
    const bf16* __restrict__ Ah, const bf16* __restrict__ Al,
    const bf16* __restrict__ Bh, const bf16* __restrict__ Bl,
    float* __restrict__ C, bf16* __restrict__ Ch, bf16* __restrict__ Cl,
    int K, int lda, int ldb, int ldc,
    long long sA, long long sB, long long sC,
    const float* __restrict__ E, int eN)
{
    extern __shared__ __align__(16) unsigned char sm[];
    const long long z = blockIdx.z;
    Ah += z * sA; Al += z * sA;
    Bh += z * sB; Bl += z * sB;
    if (OUT == 0) C += z * sC; else { Ch += z * sC; Cl += z * sC; }

    const int tid = threadIdx.x;
    const int wid = tid >> 5, lane = tid & 31;
    const int wm = wid >> 2, wn = wid & 3;
    const int m0 = blockIdx.y * 128, n0 = blockIdx.x * 128;

    // loader: row = tid>>2 (0..127), ko = (tid&3)*8 bf16 (16B granule)
    const int row = tid >> 2;
    const int ko = (tid & 3) * 8;
    const u32 smb = saddr(sm);
    const u32 sdst = smb + (u32)(row * LDR + ko) * 2;

    // ldmatrix per-thread tile offsets
    const int q = lane >> 3, lr = lane & 7;
    const int a_t = (lr + (q & 1) * 8) * LDR + (q >> 1) * 8;
    const int b_t = (lr + (q >> 1) * 8) * LDR + (q & 1) * 8;

    float acc[2][4][4];
#pragma unroll
    for (int mt = 0; mt < 2; mt++)
#pragma unroll
        for (int nt = 0; nt < 4; nt++)
#pragma unroll
            for (int e = 0; e < 4; e++) acc[mt][nt][e] = 0.f;

    const int nch = K >> 5;

#define ISSUE(c, st) do {                                                    \
        const u32 sb_ = sdst + (u32)(st) * STGB;                             \
        const size_t ao_ = (size_t)(m0 + row) * lda + (c) * 32 + ko;         \
        const size_t bo_ = (size_t)(n0 + row) * ldb + (c) * 32 + ko;         \
        cp16(sb_,             Ah + ao_);                                     \
        cp16(sb_ + MATB,      Al + ao_);                                     \
        cp16(sb_ + 2 * MATB,  Bh + bo_);                                     \
        cp16(sb_ + 3 * MATB,  Bl + bo_);                                     \
        asm volatile("cp.async.commit_group;" ::: "memory");                 \
    } while (0)

    // prologue: chunks 0..2 into stages 0..2
    ISSUE(0, 0); ISSUE(1, 1); ISSUE(2, 2);

    for (int c = 0; c < nch; c++) {
        asm volatile("cp.async.wait_group 2;" ::: "memory");
        __syncthreads();
        if (c + 3 < nch) ISSUE(c + 3, (c + 3) & 3);

        const u32 base = smb + (u32)(c & 3) * STGB;
#pragma unroll
        for (int ks = 0; ks < 32; ks += 16) {
            u32 ah[2][4], al[2][4], bh[4][2], bl[4][2];
#pragma unroll
            for (int mt = 0; mt < 2; mt++) {
                const u32 off = (u32)(a_t + (wm * 32 + mt * 16) * LDR + ks) * 2;
                ldsm4(ah[mt][0], ah[mt][1], ah[mt][2], ah[mt][3], base + off);
                ldsm4(al[mt][0], al[mt][1], al[mt][2], al[mt][3], base + off + MATB);
            }
#pragma unroll
            for (int np = 0; np < 2; np++) {
                const u32 off = (u32)(b_t + (wn * 32 + np * 16) * LDR + ks) * 2;
                u32 t0, t1, t2, t3;
                ldsm4(t0, t1, t2, t3, base + off + 2 * MATB);
                bh[2 * np][0] = t0; bh[2 * np][1] = t1;
                bh[2 * np + 1][0] = t2; bh[2 * np + 1][1] = t3;
                ldsm4(t0, t1, t2, t3, base + off + 3 * MATB);
                bl[2 * np][0] = t0; bl[2 * np][1] = t1;
                bl[2 * np + 1][0] = t2; bl[2 * np + 1][1] = t3;
            }
#pragma unroll
            for (int mt = 0; mt < 2; mt++)
#pragma unroll
                for (int nt = 0; nt < 4; nt++) {
                    mma_bf16(acc[mt][nt], ah[mt], bh[nt]);
                    mma_bf16(acc[mt][nt], ah[mt], bl[nt]);
                    mma_bf16(acc[mt][nt], al[mt], bh[nt]);
                }
        }
    }
#undef ISSUE

    // ---- epilogue ----
    const int rbase = m0 + wm * 32 + (lane >> 2);
    const int cbase = n0 + wn * 32 + (lane & 3) * 2;
#pragma unroll
    for (int mt = 0; mt < 2; mt++) {
#pragma unroll
        for (int nt = 0; nt < 4; nt++) {
            const int col = cbase + nt * 8;
#pragma unroll
            for (int half = 0; half < 2; half++) {
                const int r = rbase + mt * 16 + half * 8;
                float v0 = acc[mt][nt][half * 2];
                float v1 = acc[mt][nt][half * 2 + 1];
                if (EPI == 1) { v0 = fmaxf(v0, 0.f); v1 = fmaxf(v1, 0.f); }
                else if (EPI == 2) {
                    const float2 e = *(const float2*)&E[(size_t)r * eN + col];
                    v0 *= e.x; v1 *= e.y;
                } else if (EPI == 3) {
                    const float2 e = *(const float2*)&E[col];
                    v0 += e.x; v1 += e.y;
                }
                if (OUT == 0) {
                    *(float2*)&C[(size_t)r * ldc + col] = make_float2(v0, v1);
                } else {
                    bf16 h0, l0, h1, l1;
                    split1(v0, h0, l0); split1(v1, h1, l1);
                    *(u32*)&Ch[(size_t)r * ldc + col] =
                        ((u32)__bfloat16_as_ushort(h1) << 16) | __bfloat16_as_ushort(h0);
                    *(u32*)&Cl[(size_t)r * ldc + col] =
                        ((u32)__bfloat16_as_ushort(l1) << 16) | __bfloat16_as_ushort(l0);
                }
            }
        }
    }
}

// ---------------------------------------------------------------------------
// Softmax over dim=1 of MM[32][512][512]; emits SPLIT bf16 M (no fp32 write).
// ---------------------------------------------------------------------------
__global__ void softmax_dim1_kernel(const float* __restrict__ Mm,
                                    bf16* __restrict__ mh, bf16* __restrict__ ml)
{
    const int idx = blockIdx.x * 256 + threadIdx.x;
    const int b = idx >> 9, c = idx & 511;
    const float* p = Mm + (size_t)b * (512 * 512) + c;

    float mx = -1e30f, s = 0.f;
    for (int i = 0; i < 512; i++) {
        const float v = p[(size_t)i * 512];
        const float nm = fmaxf(mx, v);
        s = s * __expf(mx - nm) + __expf(v - nm);
        mx = nm;
    }
    const float inv = 1.f / s;
    bf16* ph = mh + (size_t)b * (512 * 512) + c;
    bf16* pl = ml + (size_t)b * (512 * 512) + c;
    for (int i = 0; i < 512; i++) {
        const float v = __expf(p[(size_t)i * 512] - mx) * inv;
        bf16 h, l; split1(v, h, l);
        ph[(size_t)i * 512] = h;
        pl[(size_t)i * 512] = l;
    }
}

// ---------------------------------------------------------------------------
// GRU v4 (UNCHANGED — measured best): 16 clusters of 8 CTAs, st.async sync.
// ---------------------------------------------------------------------------
__device__ __forceinline__ u64 pk2(float a, float b) {
    u64 r; asm("mov.b64 %0, {%1, %2};" : "=l"(r) : "f"(a), "f"(b)); return r;
}
__device__ __forceinline__ void fma2(u64& d, u64 a, u64 b) {
    asm("fma.rn.f32x2 %0, %1, %2, %0;" : "+l"(d) : "l"(a), "l"(b));
}
__device__ __forceinline__ u64 add2(u64 a, u64 b) {
    u64 d; asm("add.rn.f32x2 %0, %1, %2;" : "=l"(d) : "l"(a), "l"(b)); return d;
}
__device__ __forceinline__ float2 unpk(u64 v) {
    float2 f; asm("mov.b64 {%0, %1}, %2;" : "=f"(f.x), "=f"(f.y) : "l"(v)); return f;
}

template<int CUR, bool DO_WAIT>
__device__ __forceinline__ void gru_step(
    int t, int tid, int kq, int b0, int gi, int b_l, int hl2,
    const u64 (&w2reg)[3][16],
    u64 (&hbuf)[2][2][128], u64 (&parts)[3][2][8][32],
    u32 mb_cur, u32 parity,
    const u32 (&dd)[8], const u32 (&dm)[8],
    float br, float bz, float bn,
    float& xr_c, float& xz_c, float& xn_c,
    const float* __restrict__ xp, float* __restrict__ out)
{
    float xr_n = 0.f, xz_n = 0.f, xn_n = 0.f;
    if (tid < 64) {
        const int tn = (t + 1 < 512) ? t + 1 : 511;
        const float* p = xp + ((size_t)(b0 + b_l) * 512 + tn) * 768 + gi * 32 + hl2;
        xr_n = __ldg(p); xz_n = __ldg(p + 256); xn_n = __ldg(p + 512);
    }

    if (DO_WAIT) {
        mbar_wait(mb_cur, parity);
        if (tid == 0)
            asm volatile("mbarrier.arrive.expect_tx.shared.b64 _, [%0], %1;"
                         :: "r"(mb_cur), "r"(2048u) : "memory");
    }

    const int h_l = tid & 31;
    const u64* h0p = &hbuf[CUR][0][kq * 16];
    const u64* h1p = &hbuf[CUR][1][kq * 16];
    u64 a00 = 0, a01 = 0, a10 = 0, a11 = 0, a20 = 0, a21 = 0;
#pragma unroll
    for (int kp = 0; kp < 16; kp++) {
        const u64 ha = h0p[kp], hb = h1p[kp];
        fma2(a00, ha, w2reg[0][kp]); fma2(a01, hb, w2reg[0][kp]);
        fma2(a10, ha, w2reg[1][kp]); fma2(a11, hb, w2reg[1][kp]);
        fma2(a20, ha, w2reg[2][kp]); fma2(a21, hb, w2reg[2][kp]);
    }
    parts[0][0][kq][h_l] = a00; parts[0][1][kq][h_l] = a01;
    parts[1][0][kq][h_l] = a10; parts[1][1][kq][h_l] = a11;
    parts[2][0][kq][h_l] = a20; parts[2][1][kq][h_l] = a21;
    __syncthreads();

    if (tid < 64) {
        u64 sr = parts[0][b_l][0][hl2];
        u64 sz = parts[1][b_l][0][hl2];
        u64 sn = parts[2][b_l][0][hl2];
#pragma unroll
        for (int qq = 1; qq < 8; qq++) {
            sr = add2(sr, parts[0][b_l][qq][hl2]);
            sz = add2(sz, parts[1][b_l][qq][hl2]);
            sn = add2(sn, parts[2][b_l][qq][hl2]);
        }
        const float2 fr = unpk(sr), fz = unpk(sz), fn = unpk(sn);
        const float hr = fr.x + fr.y + br;
        const float hz = fz.x + fz.y + bz;
        const float hn = fn.x + fn.y + bn;

        const float r = 1.f / (1.f + __expf(-(xr_c + hr)));
        const float z = 1.f / (1.f + __expf(-(xz_c + hz)));
        const float n = tanhf(xn_c + r * hn);
        const float hp = ((const float*)&hbuf[CUR][b_l][0])[gi * 32 + hl2];
        const float hnew = (1.f - z) * n + z * hp;
        const u32 hbits = __float_as_uint(hnew);

#pragma unroll
        for (int rk = 0; rk < 8; rk++)
            asm volatile(
                "st.async.shared::cluster.mbarrier::complete_tx::bytes.b32 [%0], %1, [%2];"
                :: "r"(dd[rk]), "r"(hbits), "r"(dm[rk]) : "memory");

        out[((size_t)(b0 + b_l) * 512 + t) * 256 + gi * 32 + hl2] = hnew;
    }
    xr_c = xr_n; xz_c = xz_n; xn_c = xn_n;
}

__global__ void __launch_bounds__(256, 1) __cluster_dims__(8, 1, 1)
gru_kernel(const float* __restrict__ xp,
           const float* __restrict__ whh,
           const float* __restrict__ bhh,
           float* __restrict__ out)
{
    __shared__ __align__(16) u64 hbuf[2][2][128];
    __shared__ __align__(16) u64 parts[3][2][8][32];
    __shared__ __align__(8)  u64 mbars[2];

    const int tid = threadIdx.x;
    u32 gi; asm("mov.u32 %0, %%cluster_ctarank;" : "=r"(gi));
    const int b0 = (blockIdx.x >> 3) * 2;
    const int h_l = tid & 31;
    const int kq  = tid >> 5;
    const int hg  = gi * 32 + h_l;

    u64 w2reg[3][16];
#pragma unroll
    for (int g = 0; g < 3; g++) {
        const float* wr = whh + (size_t)(g * 256 + hg) * 256 + kq * 32;
#pragma unroll
        for (int kp = 0; kp < 16; kp += 2) {
            float4 v = __ldg((const float4*)(wr + kp * 2));
            w2reg[g][kp]     = pk2(v.x, v.y);
            w2reg[g][kp + 1] = pk2(v.z, v.w);
        }
    }

    const u32 mb0 = saddr(&mbars[0]);
    const u32 mb1 = saddr(&mbars[1]);
    if (tid == 0) {
        asm volatile("mbarrier.init.shared.b64 [%0], 1;" :: "r"(mb0) : "memory");
        asm volatile("mbarrier.init.shared.b64 [%0], 1;" :: "r"(mb1) : "memory");
        asm volatile("fence.proxy.async.shared::cta;" ::: "memory");
        asm volatile("mbarrier.arrive.expect_tx.shared.b64 _, [%0], %1;"
                     :: "r"(mb0), "r"(2048u) : "memory");
        asm volatile("mbarrier.arrive.expect_tx.shared.b64 _, [%0], %1;"
                     :: "r"(mb1), "r"(2048u) : "memory");
    }
    ((u64*)hbuf)[tid] = 0ull;
    ((u64*)hbuf)[tid + 256] = 0ull;
    __syncthreads();
    asm volatile("barrier.cluster.arrive.aligned;" ::: "memory");
    asm volatile("barrier.cluster.wait.aligned;" ::: "memory");

    float br = 0.f, bz = 0.f, bn = 0.f;
    int b_l = 0, hl2 = 0;
    u32 dd0[8], dd1[8], dm0[8], dm1[8];
#pragma unroll
    for (int rk = 0; rk < 8; rk++) { dd0[rk] = dd1[rk] = dm0[rk] = dm1[rk] = 0u; }
    if (tid < 64) {
        b_l = tid >> 5; hl2 = tid & 31;
        const int hgf = gi * 32 + hl2;
        br = __ldg(&bhh[hgf]);
        bz = __ldg(&bhh[256 + hgf]);
        bn = __ldg(&bhh[512 + hgf]);
        const u32 la0 = saddr(&((float*)&hbuf[0][b_l][0])[hgf]);
        const u32 la1 = saddr(&((float*)&hbuf[1][b_l][0])[hgf]);
#pragma unroll
        for (int rk = 0; rk < 8; rk++) {
            asm("mapa.shared::cluster.u32 %0, %1, %2;" : "=r"(dd0[rk]) : "r"(la0), "r"(rk));
            asm("mapa.shared::cluster.u32 %0, %1, %2;" : "=r"(dd1[rk]) : "r"(la1), "r"(rk));
            asm("mapa.shared::cluster.u32 %0, %1, %2;" : "=r"(dm0[rk]) : "r"(mb0), "r"(rk));
            asm("mapa.shared::cluster.u32 %0, %1, %2;" : "=r"(dm1[rk]) : "r"(mb1), "r"(rk));
        }
    }

    float xr_c = 0.f, xz_c = 0.f, xn_c = 0.f;
    if (tid < 64) {
        const float* p = xp + ((size_t)(b0 + b_l) * 512) * 768 + gi * 32 + hl2;
        xr_c = __ldg(p); xz_c = __ldg(p + 256); xn_c = __ldg(p + 512);
    }

    u32 p0 = 0, p1 = 0;
    gru_step<0, false>(0, tid, kq, b0, gi, b_l, hl2, w2reg, hbuf, parts,
                       mb0, 0u, dd1, dm1, br, bz, bn, xr_c, xz_c, xn_c, xp, out);
    for (int t = 1; t < 511; t += 2) {
        gru_step<1, true>(t, tid, kq, b0, gi, b_l, hl2, w2reg, hbuf, parts,
                          mb1, p1, dd0, dm0, br, bz, bn, xr_c, xz_c, xn_c, xp, out);
        p1 ^= 1u;
        gru_step<0, true>(t + 1, tid, kq, b0, gi, b_l, hl2, w2reg, hbuf, parts,
                          mb0, p0, dd1, dm1, br, bz, bn, xr_c, xz_c, xn_c, xp, out);
        p0 ^= 1u;
    }
    gru_step<1, true>(511, tid, kq, b0, gi, b_l, hl2, w2reg, hbuf, parts,
                      mb1, p1, dd0, dm0, br, bz, bn, xr_c, xz_c, xn_c, xp, out);
    mbar_wait(mb0, p0);
}

// ---------------------------------------------------------------------------
extern "C" void kernel_launch(void* const* d_in, const int* in_sizes, int n_in,
                              void* d_out, int out_size)
{
    const float* x1  = (const float*)d_in[0];
    const float* x2  = (const float*)d_in[1];
    const float* w1  = (const float*)d_in[2];
    const float* w2  = (const float*)d_in[3];
    const float* Dm  = (const float*)d_in[4];
    const float* Wm  = (const float*)d_in[5];
    const float* wih = (const float*)d_in[6];
    const float* whh = (const float*)d_in[7];
    const float* bih = (const float*)d_in[8];
    const float* bhh = (const float*)d_in[9];
    float* out = (float*)d_out;

    float* f32 = nullptr; bf16* bf = nullptr;
    cudaGetSymbolAddress((void**)&f32, g_f32);
    cudaGetSymbolAddress((void**)&bf, g_bf);

    float* MM = f32 + F_MM;
    float* XP = f32 + F_XP;

    cudaFuncSetAttribute(gemm_bb<1, 1>, cudaFuncAttributeMaxDynamicSharedMemorySize, GEMM_SMEM);
    cudaFuncSetAttribute(gemm_bb<0, 1>, cudaFuncAttributeMaxDynamicSharedMemorySize, GEMM_SMEM);
    cudaFuncSetAttribute(gemm_bb<2, 0>, cudaFuncAttributeMaxDynamicSharedMemorySize, GEMM_SMEM);
    cudaFuncSetAttribute(gemm_bb<3, 0>, cudaFuncAttributeMaxDynamicSharedMemorySize, GEMM_SMEM);

    // ---- conversions ----
    // x1 -> GG left (dst_ld 512)
    conv_split<<<4096, 256>>>(x1, bf + O_GGH, bf + O_GGL, 256, 512, 6, 16384 * 64);
    // x2 -> X2s
    conv_split<<<4096, 256>>>(x2, bf + O_X2H, bf + O_X2L, 256, 256, 6, 16384 * 64);
    // weights
    conv_split<<<64, 256>>>(w1, bf + O_W1H, bf + O_W1L, 256, 256, 6, 256 * 64);
    conv_split<<<64, 256>>>(w2, bf + O_W2H, bf + O_W2L, 256, 256, 6, 256 * 64);
    conv_split<<<384, 256>>>(wih, bf + O_WIHH, bf + O_WIHL, 512, 512, 7, 768 * 128);
    // D -> D^T split
    conv_trans<<<dim3(8, 8, 1), dim3(32, 8)>>>(Dm, bf + O_DTH, bf + O_DTL,
                                               256, 256, 0, 0);
    // x2 -> per-batch transpose [32][256][512]
    conv_trans<<<dim3(8, 16, 32), dim3(32, 8)>>>(x2, bf + O_X2TH, bf + O_X2TL,
                                                 512, 256,
                                                 (long long)512 * 256,
                                                 (long long)256 * 512);

    // ---- GEMMs ----
    // t1 = relu(x1 @ w1^T) -> T1 split          A=GG-left (lda 512)
    gemm_bb<1, 1><<<dim3(2, 128, 1), 512, GEMM_SMEM>>>(
        bf + O_GGH, bf + O_GGL, bf + O_W1H, bf + O_W1L,
        nullptr, bf + O_T1H, bf + O_T1L,
        256, 512, 256, 256, 0, 0, 0, nullptr, 0);
    // a2 = relu(x2 @ w2^T) -> A2 split
    gemm_bb<1, 1><<<dim3(2, 128, 1), 512, GEMM_SMEM>>>(
        bf + O_X2H, bf + O_X2L, bf + O_W2H, bf + O_W2L,
        nullptr, bf + O_A2H, bf + O_A2L,
        256, 256, 256, 256, 0, 0, 0, nullptr, 0);
    // a1 = t1 @ D = t1 @ (D^T)^T -> A1 split
    gemm_bb<0, 1><<<dim3(2, 128, 1), 512, GEMM_SMEM>>>(
        bf + O_T1H, bf + O_T1L, bf + O_DTH, bf + O_DTL,
        nullptr, bf + O_A1H, bf + O_A1L,
        256, 256, 256, 256, 0, 0, 0, nullptr, 0);
    // M[b] = (a1[b] @ a2[b]^T) * W -> MM fp32
    gemm_bb<2, 0><<<dim3(4, 4, 32), 512, GEMM_SMEM>>>(
        bf + O_A1H, bf + O_A1L, bf + O_A2H, bf + O_A2L,
        MM, nullptr, nullptr,
        256, 256, 256, 512,
        (long long)512 * 256, (long long)512 * 256, (long long)512 * 512, Wm, 512);
    // softmax over dim=1 -> M split
    softmax_dim1_kernel<<<64, 256>>>(MM, bf + O_MH, bf + O_ML);
    // ctx[b] = M[b] @ x2[b] = M[b] @ (x2t[b])^T -> GG right half (split)
    gemm_bb<0, 1><<<dim3(2, 4, 32), 512, GEMM_SMEM>>>(
        bf + O_MH, bf + O_ML, bf + O_X2TH, bf + O_X2TL,
        nullptr, bf + O_GGH + 256, bf + O_GGL + 256,
        512, 512, 512, 512,
        (long long)512 * 512, (long long)256 * 512, (long long)512 * 512,
        nullptr, 0);
    // xp = g @ wih^T + bih -> XP fp32
    gemm_bb<3, 0><<<dim3(6, 128, 1), 512, GEMM_SMEM>>>(
        bf + O_GGH, bf + O_GGL, bf + O_WIHH, bf + O_WIHL,
        XP, nullptr, nullptr,
        512, 512, 512, 768, 0, 0, 0, bih, 0);
    // GRU recurrence (v4, unchanged)
    gru_kernel<<<128, 256>>>(XP, whh, bhh, out);
}